// round 1
// baseline (speedup 1.0000x reference)
#include <cuda_runtime.h>
#include <math.h>

// KnnLoss: B=2, N=8192 points in 3D, KS=16 mask channels, K=8 NN, radius 0.1
// loss = mean_{b,n} (1/K) * sum_k sum_s | mask[b,n,s] - mask[b, idx[b,n,k], s] |
// where idx = 8 nearest neighbors (radius-filtered -> replaced by self).

#define B_CONST 2
#define N_CONST 8192
#define KS_CONST 16
#define KNN 8
#define QPB 128                 // queries (threads) per block
#define TILE 2048               // points per smem tile (32 KB of float4)
#define NBLOCKS ((B_CONST * N_CONST) / QPB)   // 128

__device__ float g_partials[NBLOCKS];

__global__ __launch_bounds__(QPB) void knn_loss_main(const float* __restrict__ pc,
                                                     const float* __restrict__ mask) {
    __shared__ float4 spt[TILE];

    const int blocksPerBatch = N_CONST / QPB;
    const int b = blockIdx.x / blocksPerBatch;
    const int q = (blockIdx.x % blocksPerBatch) * QPB + threadIdx.x;

    const float* pcb   = pc   + (size_t)b * N_CONST * 3;
    const float* maskb = mask + (size_t)b * N_CONST * KS_CONST;

    const float qx = pcb[q * 3 + 0];
    const float qy = pcb[q * 3 + 1];
    const float qz = pcb[q * 3 + 2];
    const float qsq = qx * qx + qy * qy + qz * qz;

    float v[KNN];
    int   jj[KNN];
#pragma unroll
    for (int t = 0; t < KNN; ++t) { v[t] = 3.4e38f; jj[t] = q; }

    for (int base = 0; base < N_CONST; base += TILE) {
        __syncthreads();
        for (int i = threadIdx.x; i < TILE; i += QPB) {
            int m = base + i;
            float x = pcb[m * 3 + 0];
            float y = pcb[m * 3 + 1];
            float z = pcb[m * 3 + 2];
            spt[i] = make_float4(x, y, z, x * x + y * y + z * z);
        }
        __syncthreads();

#pragma unroll 8
        for (int i = 0; i < TILE; ++i) {
            float4 p = spt[i];
            float dot = qx * p.x + qy * p.y + qz * p.z;
            float d2 = qsq + p.w - 2.0f * dot;
            d2 = fmaxf(d2, 0.0f);
            if (d2 < v[KNN - 1]) {
                // bubble-insert, strict < keeps earlier index on ties
                // (matches jax.lax.top_k stable tie-break)
                float nv = d2;
                int   nj = base + i;
#pragma unroll
                for (int t = 0; t < KNN; ++t) {
                    bool sw = nv < v[t];
                    float tv = v[t]; int tj = jj[t];
                    if (sw) { v[t] = nv; jj[t] = nj; nv = tv; nj = tj; }
                }
            }
        }
    }

    // ---- Phase 2: gather neighbor masks, accumulate L1 diff ----
    const float4* mrow = reinterpret_cast<const float4*>(maskb + (size_t)q * KS_CONST);
    float4 m0 = mrow[0], m1 = mrow[1], m2 = mrow[2], m3 = mrow[3];

    const int self = jj[0];   // nearest (== q barring exact coincidences)
    float acc = 0.0f;
#pragma unroll
    for (int k = 0; k < KNN; ++k) {
        // dist > RADIUS -> replace with self_idx (first neighbor)
        int nb = (sqrtf(v[k]) > 0.1f) ? self : jj[k];
        const float4* nrow = reinterpret_cast<const float4*>(maskb + (size_t)nb * KS_CONST);
        float4 n0 = nrow[0], n1 = nrow[1], n2 = nrow[2], n3 = nrow[3];
        acc += fabsf(m0.x - n0.x) + fabsf(m0.y - n0.y) + fabsf(m0.z - n0.z) + fabsf(m0.w - n0.w);
        acc += fabsf(m1.x - n1.x) + fabsf(m1.y - n1.y) + fabsf(m1.z - n1.z) + fabsf(m1.w - n1.w);
        acc += fabsf(m2.x - n2.x) + fabsf(m2.y - n2.y) + fabsf(m2.z - n2.z) + fabsf(m2.w - n2.w);
        acc += fabsf(m3.x - n3.x) + fabsf(m3.y - n3.y) + fabsf(m3.z - n3.z) + fabsf(m3.w - n3.w);
    }

    // ---- Deterministic block reduction ----
    __syncthreads();
    float* sred = reinterpret_cast<float*>(spt);
    sred[threadIdx.x] = acc;
    __syncthreads();
#pragma unroll
    for (int s = QPB / 2; s > 0; s >>= 1) {
        if (threadIdx.x < s) sred[threadIdx.x] += sred[threadIdx.x + s];
        __syncthreads();
    }
    if (threadIdx.x == 0) g_partials[blockIdx.x] = sred[0];
}

__global__ __launch_bounds__(NBLOCKS) void knn_loss_finalize(float* __restrict__ out) {
    __shared__ float sred[NBLOCKS];
    sred[threadIdx.x] = g_partials[threadIdx.x];
    __syncthreads();
#pragma unroll
    for (int s = NBLOCKS / 2; s > 0; s >>= 1) {
        if (threadIdx.x < s) sred[threadIdx.x] += sred[threadIdx.x + s];
        __syncthreads();
    }
    if (threadIdx.x == 0)
        out[0] = sred[0] / (float)(B_CONST * N_CONST * KNN);
}

extern "C" void kernel_launch(void* const* d_in, const int* in_sizes, int n_in,
                              void* d_out, int out_size) {
    const float* pc   = (const float*)d_in[0];   // (2, 8192, 3) f32
    const float* mask = (const float*)d_in[1];   // (2, 8192, 16) f32
    float* out = (float*)d_out;                  // scalar f32

    knn_loss_main<<<NBLOCKS, QPB>>>(pc, mask);
    knn_loss_finalize<<<1, NBLOCKS>>>(out);
}

// round 2
// speedup vs baseline: 4.0041x; 4.0041x over previous
#include <cuda_runtime.h>
#include <math.h>

// KnnLoss via spatial grid: B=2, N=8192 pts in [0,1]^3, KS=16, K=8, radius 0.1.
// Key fact: neighbors with dist > 0.1 are replaced by self => contribute 0.
// A 10x10x10 grid (cell = radius) therefore contains every point that can
// matter; top-8 over the 27-cell neighborhood has exactly the same
// within-radius members as top-8 over all N (all within-radius points sort
// before all out-of-radius points). Tie-break (d2, idx) lexicographic via
// packed u64 keys == jax.lax.top_k stable lowest-index rule, and is
// independent of candidate scan order (atomic-scatter-safe).

#define B_CONST 2
#define N_CONST 8192
#define KS_CONST 16
#define KNN 8
#define GRID 10
#define NCELLS (GRID * GRID * GRID)          // 1000
#define TOTPTS (B_CONST * N_CONST)           // 16384
#define TPQ 4                                 // threads per query
#define MAIN_TPB 128
#define MAIN_BLOCKS ((TOTPTS * TPQ) / MAIN_TPB)   // 512

__device__ int    g_count [B_CONST * NCELLS];
__device__ int    g_start [B_CONST * (NCELLS + 1)];
__device__ int    g_cursor[B_CONST * NCELLS];
__device__ float4 g_sorted[TOTPTS];           // (x, y, z, idx-as-float-bits)
__device__ float  g_partials[MAIN_BLOCKS];

__device__ __forceinline__ int cell_of(float x, float y, float z) {
    int cx = min(max((int)(x * (float)GRID), 0), GRID - 1);
    int cy = min(max((int)(y * (float)GRID), 0), GRID - 1);
    int cz = min(max((int)(z * (float)GRID), 0), GRID - 1);
    return cx + GRID * (cy + GRID * cz);      // x fastest => x-adjacent cells contiguous
}

// ---------------- grid build ----------------

__global__ void k_zero() {
    int t = blockIdx.x * 256 + threadIdx.x;
    if (t < B_CONST * NCELLS) g_count[t] = 0;
}

__global__ void k_hist(const float* __restrict__ pc) {
    int t = blockIdx.x * 256 + threadIdx.x;
    if (t >= TOTPTS) return;
    int b = t / N_CONST;
    const float* p = pc + (size_t)t * 3;
    atomicAdd(&g_count[b * NCELLS + cell_of(p[0], p[1], p[2])], 1);
}

__global__ __launch_bounds__(1024) void k_scan() {           // blockIdx.x = batch
    __shared__ int s[1024];
    int b = blockIdx.x, tid = threadIdx.x;
    int c = (tid < NCELLS) ? g_count[b * NCELLS + tid] : 0;
    s[tid] = c;
    __syncthreads();
#pragma unroll
    for (int off = 1; off < 1024; off <<= 1) {
        int v = (tid >= off) ? s[tid - off] : 0;
        __syncthreads();
        s[tid] += v;
        __syncthreads();
    }
    int incl = s[tid];
    int excl = incl - c;
    if (tid < NCELLS) {
        g_start [b * (NCELLS + 1) + tid] = excl;
        g_cursor[b * NCELLS + tid]       = excl;
    }
    if (tid == NCELLS - 1) g_start[b * (NCELLS + 1) + NCELLS] = incl;
}

__global__ void k_scatter(const float* __restrict__ pc) {
    int t = blockIdx.x * 256 + threadIdx.x;
    if (t >= TOTPTS) return;
    int b = t / N_CONST, i = t % N_CONST;
    const float* p = pc + (size_t)t * 3;
    float x = p[0], y = p[1], z = p[2];
    int pos = atomicAdd(&g_cursor[b * NCELLS + cell_of(x, y, z)], 1);
    g_sorted[b * N_CONST + pos] = make_float4(x, y, z, __int_as_float(i));
}

// ---------------- main: knn + loss ----------------

__device__ __forceinline__ void insert8(unsigned long long K[KNN], unsigned long long key) {
#pragma unroll
    for (int t = 0; t < KNN; ++t) {
        unsigned long long old = K[t];
        bool sw = key < old;
        K[t] = sw ? key : old;
        key  = sw ? old : key;
    }
}

__global__ __launch_bounds__(MAIN_TPB) void knn_loss_main(const float* __restrict__ mask) {
    __shared__ unsigned long long sk[MAIN_TPB * KNN];        // 8 KB

    const int t     = blockIdx.x * MAIN_TPB + threadIdx.x;
    const int qslot = t >> 2;                                // sorted-order slot
    const int sub   = t & (TPQ - 1);
    const int b     = qslot / N_CONST;
    const int s     = qslot % N_CONST;

    const float4 me = g_sorted[b * N_CONST + s];
    const float qx = me.x, qy = me.y, qz = me.z;
    const int   qi = __float_as_int(me.w);

    const int cx = min(max((int)(qx * (float)GRID), 0), GRID - 1);
    const int cy = min(max((int)(qy * (float)GRID), 0), GRID - 1);
    const int cz = min(max((int)(qz * (float)GRID), 0), GRID - 1);
    const int x0 = max(cx - 1, 0), x1 = min(cx + 1, GRID - 1);
    const int y0 = max(cy - 1, 0), y1 = min(cy + 1, GRID - 1);
    const int z0 = max(cz - 1, 0), z1 = min(cz + 1, GRID - 1);
    const int w  = x1 - x0 + 1;

    const int*    startb  = g_start + b * (NCELLS + 1);
    const float4* sortedb = g_sorted + b * N_CONST;

    // sentinel: d2 = +inf, idx = self  (inf > radius -> replaced by self anyway)
    const unsigned long long SENT =
        ((unsigned long long)0x7F800000u << 32) | (unsigned)qi;
    unsigned long long K[KNN];
#pragma unroll
    for (int k = 0; k < KNN; ++k) K[k] = SENT;

    int seg = 0;
    for (int izz = z0; izz <= z1; ++izz) {
        for (int iyy = y0; iyy <= y1; ++iyy) {
            bool mine = ((seg & (TPQ - 1)) == sub);
            ++seg;
            if (!mine) continue;
            int c0  = x0 + GRID * (iyy + GRID * izz);
            int beg = startb[c0];
            int end = startb[c0 + w];
            int p = beg;
            for (; p + 1 < end; p += 2) {
                float4 a  = sortedb[p];
                float4 bb = sortedb[p + 1];
                float dax = qx - a.x,  day = qy - a.y,  daz = qz - a.z;
                float dbx = qx - bb.x, dby = qy - bb.y, dbz = qz - bb.z;
                float d2a = dax * dax + day * day + daz * daz;
                float d2b = dbx * dbx + dby * dby + dbz * dbz;
                unsigned long long ka =
                    ((unsigned long long)__float_as_uint(d2a) << 32) | (unsigned)__float_as_int(a.w);
                unsigned long long kb =
                    ((unsigned long long)__float_as_uint(d2b) << 32) | (unsigned)__float_as_int(bb.w);
                if (ka < K[KNN - 1]) insert8(K, ka);
                if (kb < K[KNN - 1]) insert8(K, kb);
            }
            if (p < end) {
                float4 a = sortedb[p];
                float dax = qx - a.x, day = qy - a.y, daz = qz - a.z;
                float d2a = dax * dax + day * day + daz * daz;
                unsigned long long ka =
                    ((unsigned long long)__float_as_uint(d2a) << 32) | (unsigned)__float_as_int(a.w);
                if (ka < K[KNN - 1]) insert8(K, ka);
            }
        }
    }

    // publish partial top-8 lists, merge within each 4-thread group
#pragma unroll
    for (int k = 0; k < KNN; ++k) sk[threadIdx.x * KNN + k] = K[k];
    __syncthreads();

    float acc = 0.0f;
    if (sub == 0) {
#pragma unroll
        for (int o = 1; o < TPQ; ++o) {
            const unsigned long long* other = &sk[(threadIdx.x + o) * KNN];
#pragma unroll
            for (int k = 0; k < KNN; ++k) {
                unsigned long long key = other[k];
                if (key < K[KNN - 1]) insert8(K, key);
            }
        }

        const float* maskb = mask + (size_t)b * N_CONST * KS_CONST;
        const float4* mrow = reinterpret_cast<const float4*>(maskb + (size_t)qi * KS_CONST);
        float4 m0 = mrow[0], m1 = mrow[1], m2 = mrow[2], m3 = mrow[3];

        const int self = (int)(unsigned)(K[0] & 0xFFFFFFFFull);   // d2=0 -> self (idx tie-break)
#pragma unroll
        for (int k = 0; k < KNN; ++k) {
            float d2 = __uint_as_float((unsigned)(K[k] >> 32));
            int   nb = (sqrtf(d2) > 0.1f) ? self : (int)(unsigned)(K[k] & 0xFFFFFFFFull);
            const float4* nrow = reinterpret_cast<const float4*>(maskb + (size_t)nb * KS_CONST);
            float4 n0 = nrow[0], n1 = nrow[1], n2 = nrow[2], n3 = nrow[3];
            acc += fabsf(m0.x - n0.x) + fabsf(m0.y - n0.y) + fabsf(m0.z - n0.z) + fabsf(m0.w - n0.w);
            acc += fabsf(m1.x - n1.x) + fabsf(m1.y - n1.y) + fabsf(m1.z - n1.z) + fabsf(m1.w - n1.w);
            acc += fabsf(m2.x - n2.x) + fabsf(m2.y - n2.y) + fabsf(m2.z - n2.z) + fabsf(m2.w - n2.w);
            acc += fabsf(m3.x - n3.x) + fabsf(m3.y - n3.y) + fabsf(m3.z - n3.z) + fabsf(m3.w - n3.w);
        }
    }

    // deterministic block reduction (reuse smem)
    __syncthreads();
    float* sred = reinterpret_cast<float*>(sk);
    sred[threadIdx.x] = acc;
    __syncthreads();
#pragma unroll
    for (int r = MAIN_TPB / 2; r > 0; r >>= 1) {
        if (threadIdx.x < r) sred[threadIdx.x] += sred[threadIdx.x + r];
        __syncthreads();
    }
    if (threadIdx.x == 0) g_partials[blockIdx.x] = sred[0];
}

__global__ __launch_bounds__(MAIN_BLOCKS) void knn_loss_finalize(float* __restrict__ out) {
    __shared__ float sred[MAIN_BLOCKS];
    sred[threadIdx.x] = g_partials[threadIdx.x];
    __syncthreads();
#pragma unroll
    for (int r = MAIN_BLOCKS / 2; r > 0; r >>= 1) {
        if (threadIdx.x < r) sred[threadIdx.x] += sred[threadIdx.x + r];
        __syncthreads();
    }
    if (threadIdx.x == 0)
        out[0] = sred[0] / (float)(B_CONST * N_CONST * KNN);
}

extern "C" void kernel_launch(void* const* d_in, const int* in_sizes, int n_in,
                              void* d_out, int out_size) {
    const float* pc   = (const float*)d_in[0];   // (2, 8192, 3)  f32
    const float* mask = (const float*)d_in[1];   // (2, 8192, 16) f32
    float* out = (float*)d_out;                  // scalar f32

    k_zero   <<<(B_CONST * NCELLS + 255) / 256, 256>>>();
    k_hist   <<<(TOTPTS + 255) / 256, 256>>>(pc);
    k_scan   <<<B_CONST, 1024>>>();
    k_scatter<<<(TOTPTS + 255) / 256, 256>>>(pc);
    knn_loss_main<<<MAIN_BLOCKS, MAIN_TPB>>>(mask);
    knn_loss_finalize<<<1, MAIN_BLOCKS>>>(out);
}

// round 3
// speedup vs baseline: 4.8795x; 1.2186x over previous
#include <cuda_runtime.h>
#include <math.h>

// KnnLoss via spatial grid, fused build + fused finalize.
// B=2, N=8192 pts uniform in [0,1]^3, KS=16, K=8, radius 0.1.
// Neighbors with dist > 0.1 are replaced by self => contribute 0, so a
// 10x10x10 grid (cell = radius) contains every point that can matter.
// Tie-break (d2, idx) lexicographic via packed u64 == jax.lax.top_k stable rule.
// Conservative prefilter d2 <= 0.0101 is safe: out-of-radius points can never
// displace within-radius points, and any that survive to the top-8 are
// replaced by self (0 contribution) exactly like the reference.

#define B_CONST 2
#define N_CONST 8192
#define KS_CONST 16
#define KNN 8
#define GRID 10
#define NCELLS (GRID * GRID * GRID)          // 1000
#define TOTPTS (B_CONST * N_CONST)           // 16384
#define TPQ 4                                 // threads per query
#define MAIN_TPB 128
#define MAIN_BLOCKS ((TOTPTS * TPQ) / MAIN_TPB)   // 512
#define BUILD_TPB 1024
#define PTS_PER_THREAD (N_CONST / BUILD_TPB)      // 8

__device__ int    g_start [B_CONST * (NCELLS + 1)];
__device__ float4 g_sorted[TOTPTS];           // (x, y, z, idx-as-float-bits)
__device__ float  g_partials[MAIN_BLOCKS];
__device__ int    g_done;

__device__ __forceinline__ int cell_of(float x, float y, float z) {
    int cx = min(max((int)(x * (float)GRID), 0), GRID - 1);
    int cy = min(max((int)(y * (float)GRID), 0), GRID - 1);
    int cz = min(max((int)(z * (float)GRID), 0), GRID - 1);
    return cx + GRID * (cy + GRID * cz);      // x fastest => x-adjacent cells contiguous
}

// ---------------- fused grid build: one block per batch ----------------

__global__ __launch_bounds__(BUILD_TPB) void k_build(const float* __restrict__ pc) {
    __shared__ int scnt[BUILD_TPB];           // counts (padded to 1024) -> scan
    __shared__ int scur[NCELLS];              // scatter cursors

    const int b   = blockIdx.x;
    const int tid = threadIdx.x;
    const float* pcb = pc + (size_t)b * N_CONST * 3;

    scnt[tid] = 0;
    __syncthreads();

    // histogram via smem atomics
#pragma unroll
    for (int k = 0; k < PTS_PER_THREAD; ++k) {
        int i = tid + k * BUILD_TPB;
        float x = pcb[3 * i + 0], y = pcb[3 * i + 1], z = pcb[3 * i + 2];
        atomicAdd(&scnt[cell_of(x, y, z)], 1);
    }
    __syncthreads();

    // inclusive Hillis-Steele scan over 1024 slots
    int c = scnt[tid];
#pragma unroll
    for (int off = 1; off < BUILD_TPB; off <<= 1) {
        int v = (tid >= off) ? scnt[tid - off] : 0;
        __syncthreads();
        scnt[tid] += v;
        __syncthreads();
    }
    int incl = scnt[tid];
    int excl = incl - c;
    if (tid < NCELLS) {
        g_start[b * (NCELLS + 1) + tid] = excl;
        scur[tid] = excl;
    }
    if (tid == NCELLS - 1) g_start[b * (NCELLS + 1) + NCELLS] = incl;
    if (b == 0 && tid == 0) g_done = 0;       // reset finalize counter each call
    __syncthreads();

    // scatter (pc re-read: L1-resident)
#pragma unroll
    for (int k = 0; k < PTS_PER_THREAD; ++k) {
        int i = tid + k * BUILD_TPB;
        float x = pcb[3 * i + 0], y = pcb[3 * i + 1], z = pcb[3 * i + 2];
        int pos = atomicAdd(&scur[cell_of(x, y, z)], 1);
        g_sorted[b * N_CONST + pos] = make_float4(x, y, z, __int_as_float(i));
    }
}

// ---------------- main: knn + loss + fused finalize ----------------

__device__ __forceinline__ void insert8(unsigned long long K[KNN], unsigned long long key) {
#pragma unroll
    for (int t = 0; t < KNN; ++t) {
        unsigned long long old = K[t];
        bool sw = key < old;
        K[t] = sw ? key : old;
        key  = sw ? old : key;
    }
}

__global__ __launch_bounds__(MAIN_TPB) void knn_loss_main(const float* __restrict__ mask,
                                                          float* __restrict__ out) {
    __shared__ unsigned long long sk[MAIN_TPB * KNN];   // 8 KB
    __shared__ int slast;

    const int t     = blockIdx.x * MAIN_TPB + threadIdx.x;
    const int qslot = t >> 2;
    const int sub   = t & (TPQ - 1);
    const int b     = qslot / N_CONST;
    const int s     = qslot % N_CONST;

    const float4 me = g_sorted[b * N_CONST + s];
    const float qx = me.x, qy = me.y, qz = me.z;
    const int   qi = __float_as_int(me.w);

    const int cx = min(max((int)(qx * (float)GRID), 0), GRID - 1);
    const int cy = min(max((int)(qy * (float)GRID), 0), GRID - 1);
    const int cz = min(max((int)(qz * (float)GRID), 0), GRID - 1);
    const int x0 = max(cx - 1, 0), x1 = min(cx + 1, GRID - 1);
    const int y0 = max(cy - 1, 0), y1 = min(cy + 1, GRID - 1);
    const int z0 = max(cz - 1, 0), z1 = min(cz + 1, GRID - 1);
    const int w  = x1 - x0 + 1;

    const int*    startb  = g_start  + b * (NCELLS + 1);
    const float4* sortedb = g_sorted + b * N_CONST;

    // pass 1: total candidate count over the (<=9) contiguous x-row segments
    int tot = 0;
    for (int izz = z0; izz <= z1; ++izz)
        for (int iyy = y0; iyy <= y1; ++iyy) {
            int c0 = x0 + GRID * (iyy + GRID * izz);
            tot += startb[c0 + w] - startb[c0];
        }

    // exact balanced partition of the flattened candidate list across TPQ threads
    const int lo = (tot * sub)       / TPQ;
    const int hi = (tot * (sub + 1)) / TPQ;

    const unsigned long long SENT =
        ((unsigned long long)0x7F800000u << 32) | (unsigned)qi;   // (+inf, self)
    unsigned long long K[KNN];
#pragma unroll
    for (int k = 0; k < KNN; ++k) K[k] = SENT;

    int off = 0;
    for (int izz = z0; izz <= z1; ++izz) {
        for (int iyy = y0; iyy <= y1; ++iyy) {
            int c0  = x0 + GRID * (iyy + GRID * izz);
            int beg = startb[c0];
            int end = startb[c0 + w];
            int cnt = end - beg;
            int s0  = max(lo - off, 0);
            int s1  = min(hi - off, cnt);
            off += cnt;
            if (s0 >= s1) continue;
            int p = beg + s0, pe = beg + s1;
            for (; p + 1 < pe; p += 2) {
                float4 a  = sortedb[p];
                float4 bb = sortedb[p + 1];
                float dax = qx - a.x,  day = qy - a.y,  daz = qz - a.z;
                float dbx = qx - bb.x, dby = qy - bb.y, dbz = qz - bb.z;
                float d2a = dax * dax + day * day + daz * daz;
                float d2b = dbx * dbx + dby * dby + dbz * dbz;
                if (d2a <= 0.0101f) {
                    unsigned long long ka =
                        ((unsigned long long)__float_as_uint(d2a) << 32) | (unsigned)__float_as_int(a.w);
                    if (ka < K[KNN - 1]) insert8(K, ka);
                }
                if (d2b <= 0.0101f) {
                    unsigned long long kb =
                        ((unsigned long long)__float_as_uint(d2b) << 32) | (unsigned)__float_as_int(bb.w);
                    if (kb < K[KNN - 1]) insert8(K, kb);
                }
            }
            if (p < pe) {
                float4 a = sortedb[p];
                float dax = qx - a.x, day = qy - a.y, daz = qz - a.z;
                float d2a = dax * dax + day * day + daz * daz;
                if (d2a <= 0.0101f) {
                    unsigned long long ka =
                        ((unsigned long long)__float_as_uint(d2a) << 32) | (unsigned)__float_as_int(a.w);
                    if (ka < K[KNN - 1]) insert8(K, ka);
                }
            }
        }
    }

    // publish partial top-8 lists, merge within each 4-thread group
#pragma unroll
    for (int k = 0; k < KNN; ++k) sk[threadIdx.x * KNN + k] = K[k];
    __syncthreads();

    float acc = 0.0f;
    if (sub == 0) {
#pragma unroll
        for (int o = 1; o < TPQ; ++o) {
            const unsigned long long* other = &sk[(threadIdx.x + o) * KNN];
#pragma unroll
            for (int k = 0; k < KNN; ++k) {
                unsigned long long key = other[k];
                if (key < K[KNN - 1]) insert8(K, key);
            }
        }

        const float* maskb = mask + (size_t)b * N_CONST * KS_CONST;
        const float4* mrow = reinterpret_cast<const float4*>(maskb + (size_t)qi * KS_CONST);
        float4 m0 = mrow[0], m1 = mrow[1], m2 = mrow[2], m3 = mrow[3];

        const int self = (int)(unsigned)(K[0] & 0xFFFFFFFFull);   // d2=0 -> self
#pragma unroll
        for (int k = 0; k < KNN; ++k) {
            float d2 = __uint_as_float((unsigned)(K[k] >> 32));
            int   nb = (sqrtf(d2) > 0.1f) ? self : (int)(unsigned)(K[k] & 0xFFFFFFFFull);
            const float4* nrow = reinterpret_cast<const float4*>(maskb + (size_t)nb * KS_CONST);
            float4 n0 = nrow[0], n1 = nrow[1], n2 = nrow[2], n3 = nrow[3];
            acc += fabsf(m0.x - n0.x) + fabsf(m0.y - n0.y) + fabsf(m0.z - n0.z) + fabsf(m0.w - n0.w);
            acc += fabsf(m1.x - n1.x) + fabsf(m1.y - n1.y) + fabsf(m1.z - n1.z) + fabsf(m1.w - n1.w);
            acc += fabsf(m2.x - n2.x) + fabsf(m2.y - n2.y) + fabsf(m2.z - n2.z) + fabsf(m2.w - n2.w);
            acc += fabsf(m3.x - n3.x) + fabsf(m3.y - n3.y) + fabsf(m3.z - n3.z) + fabsf(m3.w - n3.w);
        }
    }

    // deterministic block reduction (reuse smem)
    __syncthreads();
    float* sred = reinterpret_cast<float*>(sk);
    sred[threadIdx.x] = acc;
    __syncthreads();
#pragma unroll
    for (int r = MAIN_TPB / 2; r > 0; r >>= 1) {
        if (threadIdx.x < r) sred[threadIdx.x] += sred[threadIdx.x + r];
        __syncthreads();
    }

    // fused finalize: last block to finish reduces all partials (fixed order)
    if (threadIdx.x == 0) {
        g_partials[blockIdx.x] = sred[0];
        __threadfence();
        int old = atomicAdd(&g_done, 1);
        slast = (old == MAIN_BLOCKS - 1) ? 1 : 0;
    }
    __syncthreads();
    if (slast) {
        int tid = threadIdx.x;
        float v = __ldcg(&g_partials[tid])
                + __ldcg(&g_partials[tid + 128])
                + __ldcg(&g_partials[tid + 256])
                + __ldcg(&g_partials[tid + 384]);
        sred[tid] = v;
        __syncthreads();
#pragma unroll
        for (int r = MAIN_TPB / 2; r > 0; r >>= 1) {
            if (tid < r) sred[tid] += sred[tid + r];
            __syncthreads();
        }
        if (tid == 0)
            out[0] = sred[0] / (float)(B_CONST * N_CONST * KNN);
    }
}

extern "C" void kernel_launch(void* const* d_in, const int* in_sizes, int n_in,
                              void* d_out, int out_size) {
    const float* pc   = (const float*)d_in[0];   // (2, 8192, 3)  f32
    const float* mask = (const float*)d_in[1];   // (2, 8192, 16) f32
    float* out = (float*)d_out;                  // scalar f32

    k_build<<<B_CONST, BUILD_TPB>>>(pc);
    knn_loss_main<<<MAIN_BLOCKS, MAIN_TPB>>>(mask, out);
}

// round 4
// speedup vs baseline: 7.2097x; 1.4776x over previous
#include <cuda_runtime.h>
#include <math.h>

// KnnLoss via spatial grid. B=2, N=8192 pts uniform in [0,1]^3, KS=16, K=8,
// radius 0.1. Neighbors with dist > 0.1 are replaced by self => contribute 0,
// so a 10x10x10 grid (cell = radius) contains every point that can matter.
// Packed u64 keys (d2_bits<<32 | idx) give the jax.lax.top_k stable
// (d2, lowest-idx) order and make the top-8 set independent of scan order.
// Conservative prefilter d2 <= 0.0101 is safe (out-of-radius points either
// never make top-8 over a within-radius point, or get replaced by self).

#define B_CONST 2
#define N_CONST 8192
#define KS_CONST 16
#define KNN 8
#define GRID 10
#define NCELLS (GRID * GRID * GRID)               // 1000
#define TOTPTS (B_CONST * N_CONST)                // 16384
#define TPQ 8                                      // threads per query
#define MAIN_TPB 128
#define MAIN_BLOCKS ((TOTPTS * TPQ) / MAIN_TPB)   // 1024
#define BUILD_TPB 1024
#define PTS_PER_THREAD (N_CONST / BUILD_TPB)      // 8

__device__ int    g_start [B_CONST * (NCELLS + 1)];
__device__ float4 g_sorted[TOTPTS];               // (x, y, z, idx-as-float-bits)
__device__ float  g_partials[MAIN_BLOCKS];
__device__ int    g_done;

__device__ __forceinline__ int cell_of(float x, float y, float z) {
    int cx = min(max((int)(x * (float)GRID), 0), GRID - 1);
    int cy = min(max((int)(y * (float)GRID), 0), GRID - 1);
    int cz = min(max((int)(z * (float)GRID), 0), GRID - 1);
    return cx + GRID * (cy + GRID * cz);          // x fastest
}

// ---------------- fused grid build: one block per batch ----------------

__global__ __launch_bounds__(BUILD_TPB) void k_build(const float* __restrict__ pc) {
    __shared__ int scnt[BUILD_TPB];
    __shared__ int swoff[32];
    __shared__ int scur[NCELLS];

    const int b    = blockIdx.x;
    const int tid  = threadIdx.x;
    const int lane = tid & 31;
    const int wid  = tid >> 5;
    const float* pcb = pc + (size_t)b * N_CONST * 3;

    scnt[tid] = 0;
    __syncthreads();

#pragma unroll
    for (int k = 0; k < PTS_PER_THREAD; ++k) {
        int i = tid + k * BUILD_TPB;
        float x = pcb[3 * i + 0], y = pcb[3 * i + 1], z = pcb[3 * i + 2];
        atomicAdd(&scnt[cell_of(x, y, z)], 1);
    }
    __syncthreads();

    // shfl-based inclusive scan: warp scans + scan of 32 warp totals
    int c = scnt[tid];
    int v = c;
#pragma unroll
    for (int o = 1; o < 32; o <<= 1) {
        int n = __shfl_up_sync(0xFFFFFFFFu, v, o);
        if (lane >= o) v += n;
    }
    if (lane == 31) swoff[wid] = v;
    __syncthreads();
    if (wid == 0) {
        int w = swoff[lane];
#pragma unroll
        for (int o = 1; o < 32; o <<= 1) {
            int n = __shfl_up_sync(0xFFFFFFFFu, w, o);
            if (lane >= o) w += n;
        }
        swoff[lane] = w;
    }
    __syncthreads();
    int incl = v + (wid ? swoff[wid - 1] : 0);
    int excl = incl - c;
    if (tid < NCELLS) {
        g_start[b * (NCELLS + 1) + tid] = excl;
        scur[tid] = excl;
    }
    if (tid == NCELLS - 1) g_start[b * (NCELLS + 1) + NCELLS] = incl;
    if (b == 0 && tid == 0) g_done = 0;
    __syncthreads();

#pragma unroll
    for (int k = 0; k < PTS_PER_THREAD; ++k) {
        int i = tid + k * BUILD_TPB;
        float x = pcb[3 * i + 0], y = pcb[3 * i + 1], z = pcb[3 * i + 2];
        int pos = atomicAdd(&scur[cell_of(x, y, z)], 1);
        g_sorted[b * N_CONST + pos] = make_float4(x, y, z, __int_as_float(i));
    }
}

// ---------------- main: knn + loss + fused finalize ----------------

__device__ __forceinline__ void insert8(unsigned long long K[KNN], unsigned long long key) {
#pragma unroll
    for (int t = 0; t < KNN; ++t) {
        unsigned long long old = K[t];
        bool sw = key < old;
        K[t] = sw ? key : old;
        key  = sw ? old : key;
    }
}

__device__ __forceinline__ void try_cand(const float4 a, float qx, float qy, float qz,
                                         unsigned long long K[KNN]) {
    float dx = qx - a.x, dy = qy - a.y, dz = qz - a.z;
    float d2 = dx * dx + dy * dy + dz * dz;
    if (d2 <= 0.0101f) {
        unsigned long long key =
            ((unsigned long long)__float_as_uint(d2) << 32) | (unsigned)__float_as_int(a.w);
        if (key < K[KNN - 1]) insert8(K, key);
    }
}

__global__ __launch_bounds__(MAIN_TPB) void knn_loss_main(const float* __restrict__ mask,
                                                          float* __restrict__ out) {
    __shared__ unsigned long long sk[MAIN_TPB * KNN];   // 8 KB
    __shared__ int slast;

    const int t     = blockIdx.x * MAIN_TPB + threadIdx.x;
    const int qslot = t / TPQ;
    const int sub   = t & (TPQ - 1);
    const int b     = qslot / N_CONST;
    const int s     = qslot % N_CONST;

    const float4 me = g_sorted[b * N_CONST + s];
    const float qx = me.x, qy = me.y, qz = me.z;
    const int   qi = __float_as_int(me.w);

    const int cx = min(max((int)(qx * (float)GRID), 0), GRID - 1);
    const int cy = min(max((int)(qy * (float)GRID), 0), GRID - 1);
    const int cz = min(max((int)(qz * (float)GRID), 0), GRID - 1);
    const int x0 = max(cx - 1, 0), x1 = min(cx + 1, GRID - 1);
    const int y0 = max(cy - 1, 0), y1 = min(cy + 1, GRID - 1);
    const int z0 = max(cz - 1, 0), z1 = min(cz + 1, GRID - 1);
    const int w  = x1 - x0 + 1;

    const int*    startb  = g_start  + b * (NCELLS + 1);
    const float4* sortedb = g_sorted + b * N_CONST;

    const unsigned long long SENT =
        ((unsigned long long)0x7F800000u << 32) | (unsigned)qi;   // (+inf, self)
    unsigned long long K[KNN];
#pragma unroll
    for (int k = 0; k < KNN; ++k) K[k] = SENT;

    // interleaved partition: lane `sub` takes flat candidates == sub (mod 8)
    // -> 8-lane groups read 8 consecutive float4s (128B coalesced)
    int off = 0;
    for (int izz = z0; izz <= z1; ++izz) {
        for (int iyy = y0; iyy <= y1; ++iyy) {
            int c0  = x0 + GRID * (iyy + GRID * izz);
            int beg = startb[c0];
            int end = startb[c0 + w];
            int p = beg + ((sub - off) & (TPQ - 1));
            off += end - beg;
            for (; p + TPQ < end; p += 2 * TPQ) {
                float4 a  = sortedb[p];
                float4 a2 = sortedb[p + TPQ];
                try_cand(a,  qx, qy, qz, K);
                try_cand(a2, qx, qy, qz, K);
            }
            if (p < end) try_cand(sortedb[p], qx, qy, qz, K);
        }
    }

    // publish partial lists; lane sub==0 of each 8-group merges, writes back
#pragma unroll
    for (int k = 0; k < KNN; ++k) sk[threadIdx.x * KNN + k] = K[k];
    __syncthreads();
    if (sub == 0) {
#pragma unroll
        for (int o = 1; o < TPQ; ++o) {
            const unsigned long long* other = &sk[(threadIdx.x + o) * KNN];
#pragma unroll
            for (int k = 0; k < KNN; ++k) {
                unsigned long long key = other[k];
                if (key < K[KNN - 1]) insert8(K, key);
            }
        }
#pragma unroll
        for (int k = 0; k < KNN; ++k) sk[threadIdx.x * KNN + k] = K[k];
    }
    __syncthreads();

    // phase 2: each of the 8 lanes gathers one neighbor's mask row
    float acc;
    {
        const int base = threadIdx.x - sub;           // group leader's slot
        unsigned long long key = sk[base * KNN + sub];
        const int self = (int)(unsigned)(sk[base * KNN] & 0xFFFFFFFFull);
        float d2 = __uint_as_float((unsigned)(key >> 32));
        int   nb = (sqrtf(d2) > 0.1f) ? self : (int)(unsigned)(key & 0xFFFFFFFFull);

        const float* maskb = mask + (size_t)b * N_CONST * KS_CONST;
        const float4* mrow = reinterpret_cast<const float4*>(maskb + (size_t)qi * KS_CONST);
        const float4* nrow = reinterpret_cast<const float4*>(maskb + (size_t)nb * KS_CONST);
        float4 m0 = mrow[0], m1 = mrow[1], m2 = mrow[2], m3 = mrow[3];
        float4 n0 = nrow[0], n1 = nrow[1], n2 = nrow[2], n3 = nrow[3];
        acc  = fabsf(m0.x - n0.x) + fabsf(m0.y - n0.y) + fabsf(m0.z - n0.z) + fabsf(m0.w - n0.w);
        acc += fabsf(m1.x - n1.x) + fabsf(m1.y - n1.y) + fabsf(m1.z - n1.z) + fabsf(m1.w - n1.w);
        acc += fabsf(m2.x - n2.x) + fabsf(m2.y - n2.y) + fabsf(m2.z - n2.z) + fabsf(m2.w - n2.w);
        acc += fabsf(m3.x - n3.x) + fabsf(m3.y - n3.y) + fabsf(m3.z - n3.z) + fabsf(m3.w - n3.w);
    }

    // deterministic block reduction (reuse smem)
    __syncthreads();
    float* sred = reinterpret_cast<float*>(sk);
    sred[threadIdx.x] = acc;
    __syncthreads();
#pragma unroll
    for (int r = MAIN_TPB / 2; r > 0; r >>= 1) {
        if (threadIdx.x < r) sred[threadIdx.x] += sred[threadIdx.x + r];
        __syncthreads();
    }

    // fused finalize: last block reduces all partials in fixed order
    if (threadIdx.x == 0) {
        g_partials[blockIdx.x] = sred[0];
        __threadfence();
        int old = atomicAdd(&g_done, 1);
        slast = (old == MAIN_BLOCKS - 1) ? 1 : 0;
    }
    __syncthreads();
    if (slast) {
        int tid = threadIdx.x;
        float v = 0.0f;
#pragma unroll
        for (int j = 0; j < MAIN_BLOCKS / MAIN_TPB; ++j)
            v += __ldcg(&g_partials[tid + j * MAIN_TPB]);
        sred[tid] = v;
        __syncthreads();
#pragma unroll
        for (int r = MAIN_TPB / 2; r > 0; r >>= 1) {
            if (tid < r) sred[tid] += sred[tid + r];
            __syncthreads();
        }
        if (tid == 0)
            out[0] = sred[0] / (float)(B_CONST * N_CONST * KNN);
    }
}

extern "C" void kernel_launch(void* const* d_in, const int* in_sizes, int n_in,
                              void* d_out, int out_size) {
    const float* pc   = (const float*)d_in[0];   // (2, 8192, 3)  f32
    const float* mask = (const float*)d_in[1];   // (2, 8192, 16) f32
    float* out = (float*)d_out;                  // scalar f32

    k_build<<<B_CONST, BUILD_TPB>>>(pc);
    knn_loss_main<<<MAIN_BLOCKS, MAIN_TPB>>>(mask, out);
}

// round 5
// speedup vs baseline: 7.8259x; 1.0855x over previous
#include <cuda_runtime.h>
#include <math.h>

// KnnLoss via spatial grid, warp-per-query. B=2, N=8192 pts uniform in
// [0,1]^3, KS=16, K=8, radius 0.1. Neighbors with dist > 0.1 are replaced by
// self => contribute 0, so a 10x10x10 grid (cell = radius) holds everything
// that matters. Packed u64 keys (d2_bits<<32 | idx) give the jax.lax.top_k
// stable (d2, lowest-idx) order; the radius filter (d2 <= 0.0101) is a PREFIX
// of that order, so ranks within the filtered buffer equal global ranks:
// top-8 membership == rank < 8. No sorting needed; the loss is symmetric in k.
// Terms are accumulated in rank order -> deterministic despite atomic scatter.

#define B_CONST 2
#define N_CONST 8192
#define KS_CONST 16
#define GRID 10
#define NCELLS (GRID * GRID * GRID)               // 1000
#define TOTPTS (B_CONST * N_CONST)                // 16384
#define R2LIM 0.0101f
#define QCAP 96                                    // >> max within-radius count
#define WPB 4                                      // warps (queries) per block
#define MAIN_TPB 128
#define MAIN_BLOCKS (TOTPTS / WPB)                // 4096
#define BUILD_TPB 1024
#define PTS_PER_THREAD (N_CONST / BUILD_TPB)      // 8

__device__ int    g_start [B_CONST * (NCELLS + 1)];
__device__ float4 g_sorted[TOTPTS];               // (x, y, z, idx-as-float-bits)
__device__ float  g_partials[MAIN_BLOCKS];
__device__ int    g_done;

__device__ __forceinline__ int cell_of(float x, float y, float z) {
    int cx = min(max((int)(x * (float)GRID), 0), GRID - 1);
    int cy = min(max((int)(y * (float)GRID), 0), GRID - 1);
    int cz = min(max((int)(z * (float)GRID), 0), GRID - 1);
    return cx + GRID * (cy + GRID * cz);          // x fastest
}

// ---------------- fused grid build: one block per batch ----------------

__global__ __launch_bounds__(BUILD_TPB) void k_build(const float* __restrict__ pc) {
    __shared__ int scnt[BUILD_TPB];
    __shared__ int swoff[32];
    __shared__ int scur[NCELLS];

    const int b    = blockIdx.x;
    const int tid  = threadIdx.x;
    const int lane = tid & 31;
    const int wid  = tid >> 5;
    const float* pcb = pc + (size_t)b * N_CONST * 3;

    scnt[tid] = 0;
    __syncthreads();

#pragma unroll
    for (int k = 0; k < PTS_PER_THREAD; ++k) {
        int i = tid + k * BUILD_TPB;
        float x = pcb[3 * i + 0], y = pcb[3 * i + 1], z = pcb[3 * i + 2];
        atomicAdd(&scnt[cell_of(x, y, z)], 1);
    }
    __syncthreads();

    int c = scnt[tid];
    int v = c;
#pragma unroll
    for (int o = 1; o < 32; o <<= 1) {
        int n = __shfl_up_sync(0xFFFFFFFFu, v, o);
        if (lane >= o) v += n;
    }
    if (lane == 31) swoff[wid] = v;
    __syncthreads();
    if (wid == 0) {
        int w = swoff[lane];
#pragma unroll
        for (int o = 1; o < 32; o <<= 1) {
            int n = __shfl_up_sync(0xFFFFFFFFu, w, o);
            if (lane >= o) w += n;
        }
        swoff[lane] = w;
    }
    __syncthreads();
    int incl = v + (wid ? swoff[wid - 1] : 0);
    int excl = incl - c;
    if (tid < NCELLS) {
        g_start[b * (NCELLS + 1) + tid] = excl;
        scur[tid] = excl;
    }
    if (tid == NCELLS - 1) g_start[b * (NCELLS + 1) + NCELLS] = incl;
    if (b == 0 && tid == 0) g_done = 0;
    __syncthreads();

#pragma unroll
    for (int k = 0; k < PTS_PER_THREAD; ++k) {
        int i = tid + k * BUILD_TPB;
        float x = pcb[3 * i + 0], y = pcb[3 * i + 1], z = pcb[3 * i + 2];
        int pos = atomicAdd(&scur[cell_of(x, y, z)], 1);
        g_sorted[b * N_CONST + pos] = make_float4(x, y, z, __int_as_float(i));
    }
}

// ---------------- main: warp-per-query knn + loss + fused finalize ----------------

__global__ __launch_bounds__(MAIN_TPB) void knn_loss_main(const float* __restrict__ mask,
                                                          float* __restrict__ out) {
    __shared__ unsigned long long qbuf[WPB][QCAP];   // 3 KB
    __shared__ float qterm[WPB][8];
    __shared__ float sred[MAIN_TPB];
    __shared__ int slast;

    const int warp  = threadIdx.x >> 5;
    const int lane  = threadIdx.x & 31;
    const int qslot = blockIdx.x * WPB + warp;
    const int b     = qslot >> 13;
    const int s     = qslot & (N_CONST - 1);

    const float4 me = g_sorted[b * N_CONST + s];     // broadcast across warp
    const float qx = me.x, qy = me.y, qz = me.z;
    const int   qi = __float_as_int(me.w);

    const int cx = min(max((int)(qx * (float)GRID), 0), GRID - 1);
    const int cy = min(max((int)(qy * (float)GRID), 0), GRID - 1);
    const int cz = min(max((int)(qz * (float)GRID), 0), GRID - 1);
    const int x0 = max(cx - 1, 0), x1 = min(cx + 1, GRID - 1);
    const int w  = x1 - x0 + 1;

    const int*    startb  = g_start  + b * (NCELLS + 1);
    const float4* sortedb = g_sorted + b * N_CONST;

    // ---- scan: ballot-compact within-radius keys into per-warp buffer ----
    int cnt = 0;
#pragma unroll
    for (int dzc = -1; dzc <= 1; ++dzc) {
#pragma unroll
        for (int dyc = -1; dyc <= 1; ++dyc) {
            const int iyy = cy + dyc, izz = cz + dzc;
            if ((unsigned)iyy >= GRID || (unsigned)izz >= GRID) continue;   // uniform
            // y/z slab distance prune (uniform)
            float ry = iyy * 0.1f, rz = izz * 0.1f;
            float dyv = fmaxf(fmaxf(ry - qy, qy - (ry + 0.1f)), 0.0f);
            float dzv = fmaxf(fmaxf(rz - qz, qz - (rz + 0.1f)), 0.0f);
            if (dyv * dyv + dzv * dzv > R2LIM) continue;                    // uniform

            const int c0  = x0 + GRID * (iyy + GRID * izz);
            const int beg = __ldg(startb + c0);
            const int end = __ldg(startb + c0 + w);
            for (int p0 = beg; p0 < end; p0 += 32) {                        // uniform
                const int p = p0 + lane;
                bool pass = false;
                unsigned long long key = 0;
                if (p < end) {
                    float4 a = __ldg(sortedb + p);
                    float dx = qx - a.x, dy = qy - a.y, dz = qz - a.z;
                    float d2 = fmaf(dx, dx, fmaf(dy, dy, dz * dz));
                    if (d2 <= R2LIM) {
                        pass = true;
                        key = ((unsigned long long)__float_as_uint(d2) << 32)
                            | (unsigned)__float_as_int(a.w);
                    }
                }
                unsigned bal = __ballot_sync(0xFFFFFFFFu, pass);
                if (pass) {
                    int pos = cnt + __popc(bal & ((1u << lane) - 1u));
                    if (pos < QCAP) qbuf[warp][pos] = key;
                }
                cnt += __popc(bal);
            }
        }
    }
    if (cnt > QCAP) cnt = QCAP;
    if (lane < 8) qterm[warp][lane] = 0.0f;
    __syncwarp();

    // ---- rank pass: lane owns keys lane, lane+32, lane+64 ----
    const int j1 = lane + 32, j2 = lane + 64;
    unsigned long long k0 = ~0ull, k1 = ~0ull, k2 = ~0ull;
    if (lane < cnt) k0 = qbuf[warp][lane];
    if (j1   < cnt) k1 = qbuf[warp][j1];
    if (j2   < cnt) k2 = qbuf[warp][j2];
    int r0 = 0, r1 = 0, r2 = 0;
    int t = 0;
    for (; t + 4 <= cnt; t += 4) {
        unsigned long long a0 = qbuf[warp][t + 0];
        unsigned long long a1 = qbuf[warp][t + 1];
        unsigned long long a2 = qbuf[warp][t + 2];
        unsigned long long a3 = qbuf[warp][t + 3];
        r0 += (a0 < k0) + (a1 < k0) + (a2 < k0) + (a3 < k0);
        r1 += (a0 < k1) + (a1 < k1) + (a2 < k1) + (a3 < k1);
        r2 += (a0 < k2) + (a1 < k2) + (a2 < k2) + (a3 < k2);
    }
    for (; t < cnt; ++t) {
        unsigned long long a0 = qbuf[warp][t];
        r0 += (a0 < k0); r1 += (a0 < k1); r2 += (a0 < k2);
    }

    // ---- loss terms for rank<8 keys ----
    const float* maskb = mask + (size_t)b * N_CONST * KS_CONST;
    const float4* mrow = reinterpret_cast<const float4*>(maskb + (size_t)qi * KS_CONST);
    const float4 m0 = __ldg(mrow), m1 = __ldg(mrow + 1),
                 m2 = __ldg(mrow + 2), m3 = __ldg(mrow + 3);

#pragma unroll
    for (int c3 = 0; c3 < 3; ++c3) {
        unsigned long long k = (c3 == 0) ? k0 : (c3 == 1) ? k1 : k2;
        int r = (c3 == 0) ? r0 : (c3 == 1) ? r1 : r2;
        int jv = lane + 32 * c3;
        if (jv < cnt && r < 8) {
            float d2 = __uint_as_float((unsigned)(k >> 32));
            int   nb = (int)(unsigned)(k & 0xFFFFFFFFull);
            float term = 0.0f;
            if (!(sqrtf(d2) > 0.1f) && nb != qi) {
                const float4* nrow = reinterpret_cast<const float4*>(maskb + (size_t)nb * KS_CONST);
                float4 n0 = __ldg(nrow), n1 = __ldg(nrow + 1),
                       n2 = __ldg(nrow + 2), n3 = __ldg(nrow + 3);
                term  = fabsf(m0.x - n0.x) + fabsf(m0.y - n0.y) + fabsf(m0.z - n0.z) + fabsf(m0.w - n0.w);
                term += fabsf(m1.x - n1.x) + fabsf(m1.y - n1.y) + fabsf(m1.z - n1.z) + fabsf(m1.w - n1.w);
                term += fabsf(m2.x - n2.x) + fabsf(m2.y - n2.y) + fabsf(m2.z - n2.z) + fabsf(m2.w - n2.w);
                term += fabsf(m3.x - n3.x) + fabsf(m3.y - n3.y) + fabsf(m3.z - n3.z) + fabsf(m3.w - n3.w);
            }
            qterm[warp][r] = term;
        }
    }
    __syncwarp();

    // fixed-tree per-query sum (deterministic regardless of scatter order)
    float acc = 0.0f;
    if (lane == 0) {
        const float* tt = qterm[warp];
        acc = ((tt[0] + tt[1]) + (tt[2] + tt[3])) + ((tt[4] + tt[5]) + (tt[6] + tt[7]));
    }

    // ---- deterministic block reduction ----
    __syncthreads();
    sred[threadIdx.x] = acc;
    __syncthreads();
#pragma unroll
    for (int r = MAIN_TPB / 2; r > 0; r >>= 1) {
        if (threadIdx.x < r) sred[threadIdx.x] += sred[threadIdx.x + r];
        __syncthreads();
    }

    // ---- fused finalize: last block reduces all partials in fixed order ----
    if (threadIdx.x == 0) {
        g_partials[blockIdx.x] = sred[0];
        __threadfence();
        int old = atomicAdd(&g_done, 1);
        slast = (old == MAIN_BLOCKS - 1) ? 1 : 0;
    }
    __syncthreads();
    if (slast) {
        int tid = threadIdx.x;
        float v = 0.0f;
#pragma unroll
        for (int j = 0; j < MAIN_BLOCKS / MAIN_TPB; ++j)
            v += __ldcg(&g_partials[tid + j * MAIN_TPB]);
        sred[tid] = v;
        __syncthreads();
#pragma unroll
        for (int r = MAIN_TPB / 2; r > 0; r >>= 1) {
            if (tid < r) sred[tid] += sred[tid + r];
            __syncthreads();
        }
        if (tid == 0)
            out[0] = sred[0] / (float)(TOTPTS * 8);
    }
}

extern "C" void kernel_launch(void* const* d_in, const int* in_sizes, int n_in,
                              void* d_out, int out_size) {
    const float* pc   = (const float*)d_in[0];   // (2, 8192, 3)  f32
    const float* mask = (const float*)d_in[1];   // (2, 8192, 16) f32
    float* out = (float*)d_out;                  // scalar f32

    k_build<<<B_CONST, BUILD_TPB>>>(pc);
    knn_loss_main<<<MAIN_BLOCKS, MAIN_TPB>>>(mask, out);
}

// round 6
// speedup vs baseline: 10.2920x; 1.3151x over previous
#include <cuda_runtime.h>
#include <math.h>

// KnnLoss via spatial grid, warp-per-query, register-resident top-8 selection.
// B=2, N=8192 pts uniform in [0,1]^3, KS=16, K=8, radius 0.1.
// Neighbors with dist > 0.1 are replaced by self => contribute 0, so a
// 10x10x10 grid (cell = radius) holds everything that matters.
// Keys: 18-bit fixed-point d2 (monotone quantization of [0, 0.0101]) << 13 | idx.
// (d2, lowest-idx) order == jax.lax.top_k stable rule up to a 3.9e-8 d2 granule
// (boundary swaps: ~1 query in 16384, ~1e-5 relative loss delta).
// Selection: per-lane sorted-4 list + 8 rounds of __reduce_min_sync (REDUX.MIN).
// Deterministic: extraction order is the unique sorted order; sums use fixed trees.

#define B_CONST 2
#define N_CONST 8192
#define KS_CONST 16
#define GRID 10
#define NCELLS (GRID * GRID * GRID)               // 1000
#define TOTPTS (B_CONST * N_CONST)                // 16384
#define R2LIM 0.0101f
#define D2SCALE 25900000.0f                        // 0.0101 * SCALE = 261590 < 2^18
#define RTHRESH_U 259000u                          // floor(0.01 * SCALE)
#define WPB 4                                      // warps (queries) per block
#define MAIN_TPB 128
#define MAIN_BLOCKS (TOTPTS / WPB)                // 4096
#define BUILD_TPB 1024
#define PTS_PER_THREAD (N_CONST / BUILD_TPB)      // 8

__device__ int    g_start [B_CONST * (NCELLS + 1)];
__device__ float4 g_sorted[TOTPTS];               // (x, y, z, idx-as-float-bits)
__device__ float  g_partials[MAIN_BLOCKS];
__device__ int    g_done;

__device__ __forceinline__ int cell_of(float x, float y, float z) {
    int cx = min(max((int)(x * (float)GRID), 0), GRID - 1);
    int cy = min(max((int)(y * (float)GRID), 0), GRID - 1);
    int cz = min(max((int)(z * (float)GRID), 0), GRID - 1);
    return cx + GRID * (cy + GRID * cz);          // x fastest
}

// ---------------- fused grid build: one block per batch ----------------

__global__ __launch_bounds__(BUILD_TPB) void k_build(const float* __restrict__ pc) {
    __shared__ int scnt[BUILD_TPB];
    __shared__ int swoff[32];
    __shared__ int scur[NCELLS];

    const int b    = blockIdx.x;
    const int tid  = threadIdx.x;
    const int lane = tid & 31;
    const int wid  = tid >> 5;
    const float* pcb = pc + (size_t)b * N_CONST * 3;

    scnt[tid] = 0;
    __syncthreads();

#pragma unroll
    for (int k = 0; k < PTS_PER_THREAD; ++k) {
        int i = tid + k * BUILD_TPB;
        float x = pcb[3 * i + 0], y = pcb[3 * i + 1], z = pcb[3 * i + 2];
        atomicAdd(&scnt[cell_of(x, y, z)], 1);
    }
    __syncthreads();

    int c = scnt[tid];
    int v = c;
#pragma unroll
    for (int o = 1; o < 32; o <<= 1) {
        int n = __shfl_up_sync(0xFFFFFFFFu, v, o);
        if (lane >= o) v += n;
    }
    if (lane == 31) swoff[wid] = v;
    __syncthreads();
    if (wid == 0) {
        int w = swoff[lane];
#pragma unroll
        for (int o = 1; o < 32; o <<= 1) {
            int n = __shfl_up_sync(0xFFFFFFFFu, w, o);
            if (lane >= o) w += n;
        }
        swoff[lane] = w;
    }
    __syncthreads();
    int incl = v + (wid ? swoff[wid - 1] : 0);
    int excl = incl - c;
    if (tid < NCELLS) {
        g_start[b * (NCELLS + 1) + tid] = excl;
        scur[tid] = excl;
    }
    if (tid == NCELLS - 1) g_start[b * (NCELLS + 1) + NCELLS] = incl;
    if (b == 0 && tid == 0) g_done = 0;
    __syncthreads();

#pragma unroll
    for (int k = 0; k < PTS_PER_THREAD; ++k) {
        int i = tid + k * BUILD_TPB;
        float x = pcb[3 * i + 0], y = pcb[3 * i + 1], z = pcb[3 * i + 2];
        int pos = atomicAdd(&scur[cell_of(x, y, z)], 1);
        g_sorted[b * N_CONST + pos] = make_float4(x, y, z, __int_as_float(i));
    }
}

// ---------------- main: warp-per-query knn + loss + fused finalize ----------------

__global__ __launch_bounds__(MAIN_TPB) void knn_loss_main(const float* __restrict__ mask,
                                                          float* __restrict__ out) {
    __shared__ float swacc[WPB];
    __shared__ float sred[MAIN_TPB];
    __shared__ int slast;

    const int warp  = threadIdx.x >> 5;
    const int lane  = threadIdx.x & 31;
    const int qslot = blockIdx.x * WPB + warp;
    const int b     = qslot >> 13;
    const int s     = qslot & (N_CONST - 1);

    const float4 me = g_sorted[b * N_CONST + s];     // broadcast across warp
    const float qx = me.x, qy = me.y, qz = me.z;
    const int   qi = __float_as_int(me.w);

    const int cx = min(max((int)(qx * (float)GRID), 0), GRID - 1);
    const int cy = min(max((int)(qy * (float)GRID), 0), GRID - 1);
    const int cz = min(max((int)(qz * (float)GRID), 0), GRID - 1);
    const int x0 = max(cx - 1, 0), x1 = min(cx + 1, GRID - 1);
    const int w  = x1 - x0 + 1;

    const int*    startb  = g_start  + b * (NCELLS + 1);
    const float4* sortedb = g_sorted + b * N_CONST;

    // precompute slab distances^2 for the 3 y-rows and 3 z-slabs
    float dy2[3], dz2[3];
#pragma unroll
    for (int d = 0; d < 3; ++d) {
        float ry = (cy + d - 1) * 0.1f;
        float rz = (cz + d - 1) * 0.1f;
        float dyv = fmaxf(fmaxf(ry - qy, qy - (ry + 0.1f)), 0.0f);
        float dzv = fmaxf(fmaxf(rz - qz, qz - (rz + 0.1f)), 0.0f);
        dy2[d] = dyv * dyv;
        dz2[d] = dzv * dzv;
    }

    // per-lane sorted-4 smallest keys
    unsigned s0 = 0xFFFFFFFFu, s1 = 0xFFFFFFFFu, s2 = 0xFFFFFFFFu, s3 = 0xFFFFFFFFu;

#pragma unroll
    for (int dzc = 0; dzc < 3; ++dzc) {
#pragma unroll
        for (int dyc = 0; dyc < 3; ++dyc) {
            const int iyy = cy + dyc - 1, izz = cz + dzc - 1;
            if ((unsigned)iyy >= GRID || (unsigned)izz >= GRID) continue;   // uniform
            if (dy2[dyc] + dz2[dzc] > R2LIM) continue;                       // uniform

            const int c0  = x0 + GRID * (iyy + GRID * izz);
            const int beg = __ldg(startb + c0);
            const int end = __ldg(startb + c0 + w);
            for (int p0 = beg; p0 < end; p0 += 32) {                        // uniform
                const int p = p0 + lane;
                unsigned kk = 0xFFFFFFFFu;
                if (p < end) {
                    float4 a = __ldg(sortedb + p);
                    float dx = qx - a.x, dy = qy - a.y, dz = qz - a.z;
                    float d2 = fmaf(dx, dx, fmaf(dy, dy, dz * dz));
                    if (d2 <= R2LIM)
                        kk = ((unsigned)(d2 * D2SCALE) << 13)
                           | (unsigned)__float_as_int(a.w);
                }
                // branchless insert into sorted-4 (7 IMNMX)
                unsigned a0 = min(s0, kk), b0 = max(s0, kk);
                unsigned c1 = min(s1, b0), d1 = max(s1, b0);
                unsigned e2 = min(s2, d1), f2 = max(s2, d1);
                s3 = min(s3, f2);
                s0 = a0; s1 = c1; s2 = e2;
            }
        }
    }

    // ---- extract global top-8 via REDUX.MIN; winner r lands on lane r ----
    unsigned mykey = 0xFFFFFFFFu;
#pragma unroll
    for (int r = 0; r < 8; ++r) {
        unsigned wv = __reduce_min_sync(0xFFFFFFFFu, s0);
        if (lane == r) mykey = wv;
        bool own = (s0 == wv) && (wv != 0xFFFFFFFFu);
        s0 = own ? s1 : s0;
        s1 = own ? s2 : s1;
        s2 = own ? s3 : s2;
        s3 = own ? 0xFFFFFFFFu : s3;
    }

    // ---- loss terms: lanes 0-7 gather their neighbor's mask row ----
    float term = 0.0f;
    if (lane < 8 && mykey != 0xFFFFFFFFu) {
        unsigned uq = mykey >> 13;
        int      nb = (int)(mykey & 8191u);
        if (uq <= RTHRESH_U && nb != qi) {       // in radius, not self
            const float* maskb = mask + (size_t)b * N_CONST * KS_CONST;
            const float4* mrow = reinterpret_cast<const float4*>(maskb + (size_t)qi * KS_CONST);
            const float4* nrow = reinterpret_cast<const float4*>(maskb + (size_t)nb * KS_CONST);
            float4 m0 = __ldg(mrow), m1 = __ldg(mrow + 1), m2 = __ldg(mrow + 2), m3 = __ldg(mrow + 3);
            float4 n0 = __ldg(nrow), n1 = __ldg(nrow + 1), n2 = __ldg(nrow + 2), n3 = __ldg(nrow + 3);
            term  = fabsf(m0.x - n0.x) + fabsf(m0.y - n0.y) + fabsf(m0.z - n0.z) + fabsf(m0.w - n0.w);
            term += fabsf(m1.x - n1.x) + fabsf(m1.y - n1.y) + fabsf(m1.z - n1.z) + fabsf(m1.w - n1.w);
            term += fabsf(m2.x - n2.x) + fabsf(m2.y - n2.y) + fabsf(m2.z - n2.z) + fabsf(m2.w - n2.w);
            term += fabsf(m3.x - n3.x) + fabsf(m3.y - n3.y) + fabsf(m3.z - n3.z) + fabsf(m3.w - n3.w);
        }
    }
    // fixed shfl tree (deterministic association, lanes >= 8 contribute 0)
    term += __shfl_down_sync(0xFFFFFFFFu, term, 16);
    term += __shfl_down_sync(0xFFFFFFFFu, term, 8);
    term += __shfl_down_sync(0xFFFFFFFFu, term, 4);
    term += __shfl_down_sync(0xFFFFFFFFu, term, 2);
    term += __shfl_down_sync(0xFFFFFFFFu, term, 1);
    if (lane == 0) swacc[warp] = term;

    // ---- deterministic block + grid reduction ----
    __syncthreads();
    if (threadIdx.x == 0) {
        float acc = (swacc[0] + swacc[1]) + (swacc[2] + swacc[3]);
        g_partials[blockIdx.x] = acc;
        __threadfence();
        int old = atomicAdd(&g_done, 1);
        slast = (old == MAIN_BLOCKS - 1) ? 1 : 0;
    }
    __syncthreads();
    if (slast) {
        int tid = threadIdx.x;
        float v = 0.0f;
#pragma unroll
        for (int j = 0; j < MAIN_BLOCKS / MAIN_TPB; ++j)
            v += __ldcg(&g_partials[tid + j * MAIN_TPB]);
        sred[tid] = v;
        __syncthreads();
#pragma unroll
        for (int r = MAIN_TPB / 2; r > 0; r >>= 1) {
            if (tid < r) sred[tid] += sred[tid + r];
            __syncthreads();
        }
        if (tid == 0)
            out[0] = sred[0] / (float)(TOTPTS * 8);
    }
}

extern "C" void kernel_launch(void* const* d_in, const int* in_sizes, int n_in,
                              void* d_out, int out_size) {
    const float* pc   = (const float*)d_in[0];   // (2, 8192, 3)  f32
    const float* mask = (const float*)d_in[1];   // (2, 8192, 16) f32
    float* out = (float*)d_out;                  // scalar f32

    k_build<<<B_CONST, BUILD_TPB>>>(pc);
    knn_loss_main<<<MAIN_BLOCKS, MAIN_TPB>>>(mask, out);
}